// round 1
// baseline (speedup 1.0000x reference)
#include <cuda_runtime.h>

// Problem constants (fixed by the dataset)
#define NE 16
#define NT 512
#define NH 2048
#define NI 1408
#define NK 6
#define NPAIR (NT * NK)   // 3072
#define QB 128            // quant block

// Tiling
#define BM 64
#define BN 64
#define BK 16

// ---------------- scratch (device globals: no runtime allocation) ----------
__device__ int   g_cnt[NE];
__device__ int   g_off[NE];
__device__ int   g_list[NPAIR];
__device__ float g_hact[(size_t)NPAIR * NI];   // SwiGLU activations per pair
__device__ float g_ypair[(size_t)NPAIR * NH];  // per-pair weighted expert output

// ---------------- routing: bucket pairs by expert ---------------------------
__global__ void routing_kernel(const int* __restrict__ sel) {
    __shared__ int s_cnt[NE], s_off[NE], s_cur[NE];
    const int tid = threadIdx.x;
    if (tid < NE) s_cnt[tid] = 0;
    __syncthreads();
    for (int p = tid; p < NPAIR; p += blockDim.x)
        atomicAdd(&s_cnt[sel[p]], 1);
    __syncthreads();
    if (tid == 0) {
        int acc = 0;
        for (int e = 0; e < NE; e++) { s_off[e] = acc; acc += s_cnt[e]; s_cur[e] = 0; }
    }
    __syncthreads();
    for (int p = tid; p < NPAIR; p += blockDim.x) {
        int e = sel[p];
        int pos = atomicAdd(&s_cur[e], 1);
        g_list[s_off[e] + pos] = p;
    }
    if (tid < NE) { g_cnt[tid] = s_cnt[tid]; g_off[tid] = s_off[tid]; }
}

// ---------------- GEMM1: gate+up + SwiGLU (per-expert grouped) --------------
// A: gathered x rows (BMxBK), B: dequant Wg/Wu (BNxBK from (I,H) row-major)
__global__ __launch_bounds__(256) void gemm1_kernel(
    const float* __restrict__ x,
    const float* __restrict__ wg, const float* __restrict__ sg,
    const float* __restrict__ wu, const float* __restrict__ su)
{
    const int e   = blockIdx.z;
    const int cnt = g_cnt[e];
    const int m0  = blockIdx.y * BM;
    if (m0 >= cnt) return;
    const int off = g_off[e];
    const int n0  = blockIdx.x * BN;   // intermediate-channel offset

    __shared__ float xs[BK][BM];
    __shared__ float gs[BK][BN];
    __shared__ float us[BK][BN];
    __shared__ int   s_pair[BM];
    __shared__ int   s_tok[BM];

    const int tid = threadIdx.x;
    if (tid < BM) {
        int idx = m0 + tid;
        int p = (idx < cnt) ? g_list[off + idx] : -1;
        s_pair[tid] = p;
        s_tok[tid]  = (p >= 0) ? (p / NK) : -1;
    }
    __syncthreads();

    const int lrow  = tid >> 2;   // 0..63
    const int lquad = tid & 3;    // 0..3
    const int tx = tid & 15, ty = tid >> 4;

    const float* wge = wg + (size_t)e * NI * NH + (size_t)(n0 + lrow) * NH;
    const float* wue = wu + (size_t)e * NI * NH + (size_t)(n0 + lrow) * NH;
    const int sbase = e * (NI / QB) * (NH / QB) + (n0 / QB) * (NH / QB);
    const int tok = s_tok[lrow];
    const float* xrow = (tok >= 0) ? (x + (size_t)tok * NH) : x;

    float aG[4][4];
    float aU[4][4];
#pragma unroll
    for (int i = 0; i < 4; i++)
#pragma unroll
        for (int j = 0; j < 4; j++) { aG[i][j] = 0.f; aU[i][j] = 0.f; }

    for (int k0 = 0; k0 < NH; k0 += BK) {
        float4 xv = make_float4(0.f, 0.f, 0.f, 0.f);
        if (tok >= 0)
            xv = *reinterpret_cast<const float4*>(xrow + k0 + lquad * 4);
        const float scg = __ldg(sg + sbase + (k0 / QB));
        const float scu = __ldg(su + sbase + (k0 / QB));
        const float4 gv = *reinterpret_cast<const float4*>(wge + k0 + lquad * 4);
        const float4 uv = *reinterpret_cast<const float4*>(wue + k0 + lquad * 4);

        __syncthreads();
        xs[lquad * 4 + 0][lrow] = xv.x;
        xs[lquad * 4 + 1][lrow] = xv.y;
        xs[lquad * 4 + 2][lrow] = xv.z;
        xs[lquad * 4 + 3][lrow] = xv.w;
        gs[lquad * 4 + 0][lrow] = gv.x * scg;
        gs[lquad * 4 + 1][lrow] = gv.y * scg;
        gs[lquad * 4 + 2][lrow] = gv.z * scg;
        gs[lquad * 4 + 3][lrow] = gv.w * scg;
        us[lquad * 4 + 0][lrow] = uv.x * scu;
        us[lquad * 4 + 1][lrow] = uv.y * scu;
        us[lquad * 4 + 2][lrow] = uv.z * scu;
        us[lquad * 4 + 3][lrow] = uv.w * scu;
        __syncthreads();

#pragma unroll
        for (int kk = 0; kk < BK; kk++) {
            const float4 a  = *reinterpret_cast<const float4*>(&xs[kk][ty * 4]);
            const float4 bg = *reinterpret_cast<const float4*>(&gs[kk][tx * 4]);
            const float4 bu = *reinterpret_cast<const float4*>(&us[kk][tx * 4]);
            const float av[4]  = {a.x, a.y, a.z, a.w};
            const float bgv[4] = {bg.x, bg.y, bg.z, bg.w};
            const float buv[4] = {bu.x, bu.y, bu.z, bu.w};
#pragma unroll
            for (int i = 0; i < 4; i++)
#pragma unroll
                for (int j = 0; j < 4; j++) {
                    aG[i][j] = fmaf(av[i], bgv[j], aG[i][j]);
                    aU[i][j] = fmaf(av[i], buv[j], aU[i][j]);
                }
        }
    }

    // SwiGLU epilogue -> g_hact[pair][n0 + tx*4 .. +3]
#pragma unroll
    for (int i = 0; i < 4; i++) {
        const int m = ty * 4 + i;
        const int p = s_pair[m];
        if (p < 0) continue;
        float4 hv;
        {
            float g0 = aG[i][0], g1 = aG[i][1], g2 = aG[i][2], g3 = aG[i][3];
            hv.x = (g0 / (1.f + __expf(-g0))) * aU[i][0];
            hv.y = (g1 / (1.f + __expf(-g1))) * aU[i][1];
            hv.z = (g2 / (1.f + __expf(-g2))) * aU[i][2];
            hv.w = (g3 / (1.f + __expf(-g3))) * aU[i][3];
        }
        *reinterpret_cast<float4*>(&g_hact[(size_t)p * NI + n0 + tx * 4]) = hv;
    }
}

// ---------------- GEMM2: down proj, routing weight folded in ----------------
__global__ __launch_bounds__(256) void gemm2_kernel(
    const float* __restrict__ wd, const float* __restrict__ sd,
    const float* __restrict__ rw)
{
    const int e   = blockIdx.z;
    const int cnt = g_cnt[e];
    const int m0  = blockIdx.y * BM;
    if (m0 >= cnt) return;
    const int off = g_off[e];
    const int n0  = blockIdx.x * BN;   // hidden-channel offset

    __shared__ float as_[BK][BM];
    __shared__ float bs[BK][BN];
    __shared__ int   s_pair[BM];
    __shared__ float s_rw[BM];

    const int tid = threadIdx.x;
    if (tid < BM) {
        int idx = m0 + tid;
        int p = (idx < cnt) ? g_list[off + idx] : -1;
        s_pair[tid] = p;
        s_rw[tid]   = (p >= 0) ? rw[p] : 0.f;
    }
    __syncthreads();

    const int lrow  = tid >> 2;
    const int lquad = tid & 3;
    const int tx = tid & 15, ty = tid >> 4;

    const float* wde = wd + (size_t)e * NH * NI + (size_t)(n0 + lrow) * NI;
    const int sbase = e * (NH / QB) * (NI / QB) + (n0 / QB) * (NI / QB);
    const int p = s_pair[lrow];
    const float* arow = (p >= 0) ? (g_hact + (size_t)p * NI) : g_hact;

    float acc[4][4];
#pragma unroll
    for (int i = 0; i < 4; i++)
#pragma unroll
        for (int j = 0; j < 4; j++) acc[i][j] = 0.f;

    for (int k0 = 0; k0 < NI; k0 += BK) {
        float4 av = make_float4(0.f, 0.f, 0.f, 0.f);
        if (p >= 0)
            av = *reinterpret_cast<const float4*>(arow + k0 + lquad * 4);
        const float sc = __ldg(sd + sbase + (k0 / QB));
        const float4 bv = *reinterpret_cast<const float4*>(wde + k0 + lquad * 4);

        __syncthreads();
        as_[lquad * 4 + 0][lrow] = av.x;
        as_[lquad * 4 + 1][lrow] = av.y;
        as_[lquad * 4 + 2][lrow] = av.z;
        as_[lquad * 4 + 3][lrow] = av.w;
        bs[lquad * 4 + 0][lrow] = bv.x * sc;
        bs[lquad * 4 + 1][lrow] = bv.y * sc;
        bs[lquad * 4 + 2][lrow] = bv.z * sc;
        bs[lquad * 4 + 3][lrow] = bv.w * sc;
        __syncthreads();

#pragma unroll
        for (int kk = 0; kk < BK; kk++) {
            const float4 a = *reinterpret_cast<const float4*>(&as_[kk][ty * 4]);
            const float4 b = *reinterpret_cast<const float4*>(&bs[kk][tx * 4]);
            const float av4[4] = {a.x, a.y, a.z, a.w};
            const float bv4[4] = {b.x, b.y, b.z, b.w};
#pragma unroll
            for (int i = 0; i < 4; i++)
#pragma unroll
                for (int j = 0; j < 4; j++)
                    acc[i][j] = fmaf(av4[i], bv4[j], acc[i][j]);
        }
    }

#pragma unroll
    for (int i = 0; i < 4; i++) {
        const int m = ty * 4 + i;
        const int pp = s_pair[m];
        if (pp < 0) continue;
        const float w = s_rw[m];
        float4 yv;
        yv.x = w * acc[i][0];
        yv.y = w * acc[i][1];
        yv.z = w * acc[i][2];
        yv.w = w * acc[i][3];
        *reinterpret_cast<float4*>(&g_ypair[(size_t)pp * NH + n0 + tx * 4]) = yv;
    }
}

// ---------------- combine: out[t,h] = sum_k ypair[t*K+k, h] -----------------
__global__ void combine_kernel(float* __restrict__ out) {
    const int idx = blockIdx.x * blockDim.x + threadIdx.x;
    if (idx >= NT * NH) return;
    const int t = idx >> 11;       // / NH (2048)
    const int h = idx & (NH - 1);
    float s = 0.f;
#pragma unroll
    for (int k = 0; k < NK; k++)
        s += g_ypair[(size_t)(t * NK + k) * NH + h];
    out[idx] = s;
}

// ---------------- launch ----------------------------------------------------
extern "C" void kernel_launch(void* const* d_in, const int* in_sizes, int n_in,
                              void* d_out, int out_size) {
    const float* x   = (const float*)d_in[0];
    const float* gw  = (const float*)d_in[1];
    const float* gsc = (const float*)d_in[2];
    const float* uw  = (const float*)d_in[3];
    const float* usc = (const float*)d_in[4];
    const float* dw  = (const float*)d_in[5];
    const float* dsc = (const float*)d_in[6];
    const float* rw  = (const float*)d_in[7];
    const int*   sel = (const int*)d_in[8];
    float* out = (float*)d_out;

    routing_kernel<<<1, 256>>>(sel);

    dim3 g1(NI / BN, NPAIR / BM, NE);   // (22, 48, 16)
    gemm1_kernel<<<g1, 256>>>(x, gw, gsc, uw, usc);

    dim3 g2(NH / BN, NPAIR / BM, NE);   // (32, 48, 16)
    gemm2_kernel<<<g2, 256>>>(dw, dsc, rw);

    combine_kernel<<<(NT * NH + 255) / 256, 256>>>(out);
}

// round 3
// speedup vs baseline: 3.2215x; 3.2215x over previous
#include <cuda_runtime.h>
#include <cstdint>

// Problem constants
#define NE 16
#define NT 512
#define NH 2048
#define NI 1408
#define NK 6
#define NPAIR (NT * NK)   // 3072
#define QB 128

// ---------------- scratch (device globals) ----------------------------------
__device__ int   g_cnt[NE];
__device__ int   g_off[NE];
__device__ int   g_list[NPAIR];
__device__ float g_hact[(size_t)NPAIR * NI];   // expert-sorted SwiGLU activations
__device__ float g_ypair[(size_t)NPAIR * NH];  // per-pair weighted expert output

// ---------------- helpers ----------------------------------------------------
__device__ __forceinline__ uint32_t smem_u32(const void* p) {
    uint32_t a;
    asm("{ .reg .u64 t; cvta.to.shared.u64 t, %1; cvt.u32.u64 %0, t; }"
        : "=r"(a) : "l"(p));
    return a;
}

// load fp32 from shared, convert to tf32 (round-to-nearest: unbiased)
__device__ __forceinline__ uint32_t lds_tf32(uint32_t a) {
    float v;
    asm volatile("ld.shared.f32 %0, [%1];" : "=f"(v) : "r"(a));
    uint32_t r;
    asm volatile("cvt.rna.tf32.f32 %0, %1;" : "=r"(r) : "f"(v));
    return r;
}

__device__ __forceinline__ void mma8(float* c, const uint32_t* a,
                                     uint32_t b0, uint32_t b1) {
    asm volatile(
        "mma.sync.aligned.m16n8k8.row.col.f32.tf32.tf32.f32 "
        "{%0,%1,%2,%3}, {%4,%5,%6,%7}, {%8,%9}, {%0,%1,%2,%3};"
        : "+f"(c[0]), "+f"(c[1]), "+f"(c[2]), "+f"(c[3])
        : "r"(a[0]), "r"(a[1]), "r"(a[2]), "r"(a[3]), "r"(b0), "r"(b1));
}

#define CPA16(dst, src, sz) \
    asm volatile("cp.async.cg.shared.global [%0], [%1], 16, %2;" \
                 :: "r"(dst), "l"(src), "r"(sz) : "memory")
#define CPC()  asm volatile("cp.async.commit_group;" ::: "memory")
#define CPW0() asm volatile("cp.async.wait_group 0;" ::: "memory")
#define CPW1() asm volatile("cp.async.wait_group 1;" ::: "memory")
#define CPW2() asm volatile("cp.async.wait_group 2;" ::: "memory")

// ---------------- routing ----------------------------------------------------
__global__ void routing_kernel(const int* __restrict__ sel) {
    __shared__ int s_cnt[NE], s_off[NE], s_cur[NE];
    const int tid = threadIdx.x;
    if (tid < NE) s_cnt[tid] = 0;
    __syncthreads();
    for (int p = tid; p < NPAIR; p += blockDim.x)
        atomicAdd(&s_cnt[sel[p]], 1);
    __syncthreads();
    if (tid == 0) {
        int acc = 0;
        for (int e = 0; e < NE; e++) { s_off[e] = acc; acc += s_cnt[e]; s_cur[e] = 0; }
    }
    __syncthreads();
    for (int p = tid; p < NPAIR; p += blockDim.x) {
        int e = sel[p];
        int pos = atomicAdd(&s_cur[e], 1);
        g_list[s_off[e] + pos] = p;
    }
    if (tid < NE) { g_cnt[tid] = s_cnt[tid]; g_off[tid] = s_off[tid]; }
}

extern __shared__ char dynsm[];

// ---------------- GEMM1: gate+up tf32 mma.sync + SwiGLU ----------------------
// CTA: 128 pairs x 128 intermediate channels. K = NH (2048), BK = 32.
#define STG1 49152   // A(16K) + Wg(16K) + Wu(16K) per stage

__global__ void __launch_bounds__(256, 1) gemm1_kernel(
    const float* __restrict__ x,
    const float* __restrict__ wg, const float* __restrict__ sg,
    const float* __restrict__ wu, const float* __restrict__ su)
{
    const int e   = blockIdx.z;
    const int cnt = g_cnt[e];
    const int m0  = blockIdx.y * 128;
    if (m0 >= cnt) return;
    const int eoff = g_off[e];
    const int n0   = blockIdx.x * 128;
    const int tid  = threadIdx.x;

    int* s_tok = (int*)dynsm;
    const uint32_t tb = smem_u32(dynsm) + 1024;

    if (tid < 128) {
        int mi = m0 + tid;
        s_tok[tid] = (mi < cnt) ? (g_list[eoff + mi] / NK) : -1;
    }
    __syncthreads();

    const float* wge = wg + (size_t)e * NI * NH + (size_t)n0 * NH;
    const float* wue = wu + (size_t)e * NI * NH + (size_t)n0 * NH;
    const int scb = e * (NI / QB) * (NH / QB) + (n0 >> 7) * (NH / QB);

    auto load1 = [&](int c, int s) {
        const int k0 = c * 32;
        const uint32_t ab = tb + (uint32_t)s * STG1;
#pragma unroll
        for (int it = 0; it < 4; ++it) {
            const int idx = tid + (it << 8);
            const int r  = idx >> 3;
            const int cc = idx & 7;
            const uint32_t doff = (uint32_t)((r << 7) + (((cc + (r & 7)) & 7) << 4));
            const int tok = s_tok[r];
            const float* asrc = x + (size_t)(tok >= 0 ? tok : 0) * NH + k0 + (cc << 2);
            CPA16(ab + doff, asrc, (tok >= 0) ? 16 : 0);
            CPA16(ab + 16384 + doff, wge + (size_t)r * NH + k0 + (cc << 2), 16);
            CPA16(ab + 32768 + doff, wue + (size_t)r * NH + k0 + (cc << 2), 16);
        }
        CPC();
    };

    const int lane = tid & 31, warp = tid >> 5;
    const int gq = lane >> 2, tq = lane & 3;
    const int wm = warp & 3, wn = warp >> 2;

    float accG[2][8][4];
    float accU[2][8][4];
#pragma unroll
    for (int mi = 0; mi < 2; mi++)
#pragma unroll
        for (int ni = 0; ni < 8; ni++)
#pragma unroll
            for (int q = 0; q < 4; q++) { accG[mi][ni][q] = 0.f; accU[mi][ni][q] = 0.f; }

    float sg_c = __ldg(sg + scb);
    float su_c = __ldg(su + scb);

    const int C = NH / 32;  // 64 chunks, 4 chunks per quant block
    load1(0, 0);
    load1(1, 1);

    for (int c = 0; c < C; ++c) {
        const int s = c % 3;
        if (c + 2 < C) load1(c + 2, (c + 2) % 3);
        if (c + 2 < C)      { CPW2(); }
        else if (c + 1 < C) { CPW1(); }
        else                { CPW0(); }
        __syncthreads();

        const uint32_t As = tb + (uint32_t)s * STG1;
        const uint32_t Bg = As + 16384;
        const uint32_t Bu = As + 32768;
#pragma unroll
        for (int kk = 0; kk < 4; kk++) {
            const uint32_t ca  = (uint32_t)(((kk * 8 + tq     + 4 * gq) & 31) << 2);
            const uint32_t ca4 = (uint32_t)(((kk * 8 + tq + 4 + 4 * gq) & 31) << 2);
            uint32_t a[2][4];
#pragma unroll
            for (int mi = 0; mi < 2; mi++) {
                const uint32_t base = As + (uint32_t)((wm * 32 + mi * 16 + gq) << 7);
                a[mi][0] = lds_tf32(base + ca);
                a[mi][1] = lds_tf32(base + 1024 + ca);
                a[mi][2] = lds_tf32(base + ca4);
                a[mi][3] = lds_tf32(base + 1024 + ca4);
            }
#pragma unroll
            for (int ni = 0; ni < 8; ni++) {
                const uint32_t nb = (uint32_t)((wn * 64 + ni * 8 + gq) << 7);
                uint32_t b0 = lds_tf32(Bg + nb + ca);
                uint32_t b1 = lds_tf32(Bg + nb + ca4);
                mma8(accG[0][ni], a[0], b0, b1);
                mma8(accG[1][ni], a[1], b0, b1);
                uint32_t u0 = lds_tf32(Bu + nb + ca);
                uint32_t u1 = lds_tf32(Bu + nb + ca4);
                mma8(accU[0][ni], a[0], u0, u1);
                mma8(accU[1][ni], a[1], u0, u1);
            }
        }
        __syncthreads();

        // block-scale boundary: acc <- acc * s_b / s_{b+1}
        if ((c & 3) == 3 && c + 1 < C) {
            const int b = (c >> 2) + 1;
            const float sgn = __ldg(sg + scb + b);
            const float sun = __ldg(su + scb + b);
            const float rg = sg_c / sgn, ru = su_c / sun;
            sg_c = sgn; su_c = sun;
#pragma unroll
            for (int mi = 0; mi < 2; mi++)
#pragma unroll
                for (int ni = 0; ni < 8; ni++)
#pragma unroll
                    for (int q = 0; q < 4; q++) {
                        accG[mi][ni][q] *= rg;
                        accU[mi][ni][q] *= ru;
                    }
        }
    }

    // epilogue: final scale + SwiGLU, write sorted activations
#pragma unroll
    for (int mi = 0; mi < 2; mi++) {
#pragma unroll
        for (int half = 0; half < 2; half++) {
            const int rr = wm * 32 + mi * 16 + gq + half * 8;
            const int gm = m0 + rr;
            if (gm < cnt) {
                float* dst = g_hact + (size_t)(eoff + gm) * NI + n0 + wn * 64 + 2 * tq;
#pragma unroll
                for (int ni = 0; ni < 8; ni++) {
                    float g0 = accG[mi][ni][half * 2 + 0] * sg_c;
                    float g1 = accG[mi][ni][half * 2 + 1] * sg_c;
                    float u0 = accU[mi][ni][half * 2 + 0] * su_c;
                    float u1 = accU[mi][ni][half * 2 + 1] * su_c;
                    float2 h;
                    h.x = g0 / (1.f + __expf(-g0)) * u0;
                    h.y = g1 / (1.f + __expf(-g1)) * u1;
                    *(float2*)(dst + ni * 8) = h;
                }
            }
        }
    }
}

// ---------------- GEMM2: down proj tf32 mma.sync, scale+rw in epilogue -------
#define STG2 32768   // A(16K) + Wd(16K) per stage

__global__ void __launch_bounds__(256, 2) gemm2_kernel(
    const float* __restrict__ wd, const float* __restrict__ sd,
    const float* __restrict__ rw)
{
    const int e   = blockIdx.z;
    const int cnt = g_cnt[e];
    const int m0  = blockIdx.y * 128;
    if (m0 >= cnt) return;
    const int eoff = g_off[e];
    const int n0   = blockIdx.x * 128;
    const int tid  = threadIdx.x;

    int*   s_pair = (int*)dynsm;
    float* s_rw   = (float*)(dynsm + 512);
    const uint32_t tb = smem_u32(dynsm) + 1024;

    if (tid < 128) {
        int mi = m0 + tid;
        int p = (mi < cnt) ? g_list[eoff + mi] : -1;
        s_pair[tid] = p;
        s_rw[tid]   = (p >= 0) ? rw[p] : 0.f;
    }
    __syncthreads();

    const float* wde = wd + (size_t)e * NH * NI + (size_t)n0 * NI;
    const int scb = e * (NH / QB) * (NI / QB) + (n0 >> 7) * (NI / QB);

    auto load2 = [&](int c, int s) {
        const int k0 = c * 32;
        const uint32_t ab = tb + (uint32_t)s * STG2;
#pragma unroll
        for (int it = 0; it < 4; ++it) {
            const int idx = tid + (it << 8);
            const int r  = idx >> 3;
            const int cc = idx & 7;
            const uint32_t doff = (uint32_t)((r << 7) + (((cc + (r & 7)) & 7) << 4));
            const int ok = (m0 + r < cnt) ? 16 : 0;
            CPA16(ab + doff,
                  g_hact + (size_t)(eoff + m0 + r) * NI + k0 + (cc << 2), ok);
            CPA16(ab + 16384 + doff, wde + (size_t)r * NI + k0 + (cc << 2), 16);
        }
        CPC();
    };

    const int lane = tid & 31, warp = tid >> 5;
    const int gq = lane >> 2, tq = lane & 3;
    const int wm = warp & 3, wn = warp >> 2;

    float acc[2][8][4];
#pragma unroll
    for (int mi = 0; mi < 2; mi++)
#pragma unroll
        for (int ni = 0; ni < 8; ni++)
#pragma unroll
            for (int q = 0; q < 4; q++) acc[mi][ni][q] = 0.f;

    float sd_c = __ldg(sd + scb);

    const int C = NI / 32;  // 44 chunks, 11 quant blocks
    load2(0, 0);
    load2(1, 1);

    for (int c = 0; c < C; ++c) {
        const int s = c % 3;
        if (c + 2 < C) load2(c + 2, (c + 2) % 3);
        if (c + 2 < C)      { CPW2(); }
        else if (c + 1 < C) { CPW1(); }
        else                { CPW0(); }
        __syncthreads();

        const uint32_t As = tb + (uint32_t)s * STG2;
        const uint32_t Bs = As + 16384;
#pragma unroll
        for (int kk = 0; kk < 4; kk++) {
            const uint32_t ca  = (uint32_t)(((kk * 8 + tq     + 4 * gq) & 31) << 2);
            const uint32_t ca4 = (uint32_t)(((kk * 8 + tq + 4 + 4 * gq) & 31) << 2);
            uint32_t a[2][4];
#pragma unroll
            for (int mi = 0; mi < 2; mi++) {
                const uint32_t base = As + (uint32_t)((wm * 32 + mi * 16 + gq) << 7);
                a[mi][0] = lds_tf32(base + ca);
                a[mi][1] = lds_tf32(base + 1024 + ca);
                a[mi][2] = lds_tf32(base + ca4);
                a[mi][3] = lds_tf32(base + 1024 + ca4);
            }
#pragma unroll
            for (int ni = 0; ni < 8; ni++) {
                const uint32_t nb = (uint32_t)((wn * 64 + ni * 8 + gq) << 7);
                uint32_t b0 = lds_tf32(Bs + nb + ca);
                uint32_t b1 = lds_tf32(Bs + nb + ca4);
                mma8(acc[0][ni], a[0], b0, b1);
                mma8(acc[1][ni], a[1], b0, b1);
            }
        }
        __syncthreads();

        if ((c & 3) == 3 && c + 1 < C) {
            const int b = (c >> 2) + 1;
            const float sdn = __ldg(sd + scb + b);
            const float rsc = sd_c / sdn;
            sd_c = sdn;
#pragma unroll
            for (int mi = 0; mi < 2; mi++)
#pragma unroll
                for (int ni = 0; ni < 8; ni++)
#pragma unroll
                    for (int q = 0; q < 4; q++) acc[mi][ni][q] *= rsc;
        }
    }

#pragma unroll
    for (int mi = 0; mi < 2; mi++) {
#pragma unroll
        for (int half = 0; half < 2; half++) {
            const int rr = wm * 32 + mi * 16 + gq + half * 8;
            const int gm = m0 + rr;
            if (gm < cnt) {
                const int p = s_pair[rr + (m0 ? 0 : 0) + 0 + (gm - m0) - rr];  // = s_pair[gm-m0]
                const float w = s_rw[gm - m0] * sd_c;
                if (p >= 0) {
                    float* dst = g_ypair + (size_t)p * NH + n0 + wn * 64 + 2 * tq;
#pragma unroll
                    for (int ni = 0; ni < 8; ni++) {
                        float2 v;
                        v.x = acc[mi][ni][half * 2 + 0] * w;
                        v.y = acc[mi][ni][half * 2 + 1] * w;
                        *(float2*)(dst + ni * 8) = v;
                    }
                }
            }
        }
    }
}

// ---------------- combine ----------------------------------------------------
__global__ void combine_kernel(float* __restrict__ out) {
    const int idx = blockIdx.x * blockDim.x + threadIdx.x;
    if (idx >= NT * NH / 4) return;
    const int t  = idx / (NH / 4);
    const int h4 = idx - t * (NH / 4);
    float4 s = make_float4(0.f, 0.f, 0.f, 0.f);
#pragma unroll
    for (int k = 0; k < NK; k++) {
        const float4 v = *(const float4*)(g_ypair + (size_t)(t * NK + k) * NH + h4 * 4);
        s.x += v.x; s.y += v.y; s.z += v.z; s.w += v.w;
    }
    *(float4*)(out + (size_t)t * NH + h4 * 4) = s;
}

// ---------------- launch -----------------------------------------------------
#define SMEM1 (1024 + 3 * STG1)  // 148480
#define SMEM2 (1024 + 3 * STG2)  //  99328

extern "C" void kernel_launch(void* const* d_in, const int* in_sizes, int n_in,
                              void* d_out, int out_size) {
    const float* x   = (const float*)d_in[0];
    const float* gw  = (const float*)d_in[1];
    const float* gsc = (const float*)d_in[2];
    const float* uw  = (const float*)d_in[3];
    const float* usc = (const float*)d_in[4];
    const float* dw  = (const float*)d_in[5];
    const float* dsc = (const float*)d_in[6];
    const float* rw  = (const float*)d_in[7];
    const int*   sel = (const int*)d_in[8];
    float* out = (float*)d_out;

    static int configured = 0;
    if (!configured) {
        cudaFuncSetAttribute(gemm1_kernel, cudaFuncAttributeMaxDynamicSharedMemorySize, SMEM1);
        cudaFuncSetAttribute(gemm2_kernel, cudaFuncAttributeMaxDynamicSharedMemorySize, SMEM2);
        configured = 1;
    }

    routing_kernel<<<1, 256>>>(sel);

    dim3 g1(NI / 128, NPAIR / 128, NE);   // (11, 24, 16)
    gemm1_kernel<<<g1, 256, SMEM1>>>(x, gw, gsc, uw, usc);

    dim3 g2(NH / 128, NPAIR / 128, NE);   // (16, 24, 16)
    gemm2_kernel<<<g2, 256, SMEM2>>>(dw, dsc, rw);

    combine_kernel<<<(NT * NH / 4 + 255) / 256, 256>>>(out);
}